// round 8
// baseline (speedup 1.0000x reference)
#include <cuda_runtime.h>
#include <cstdint>

#define LL   50
#define DD   64
#define EE   128
#define UU   256     // hidden units total
#define UH   128     // hidden units per pass
#define NT   512     // 16 warps, 1 CTA/SM, 2 batches per CTA

#define FFMA2(acc, w, k) asm("fma.rn.f32x2 %0, %1, %2, %0;" : "+l"(acc) : "l"(w), "l"(k))
#define PACK2(dst, f)    asm("mov.b64 %0, {%1, %1};" : "=l"(dst) : "r"(__float_as_uint(f)))
#define UNPK2(lo, hi, s) do { unsigned _ulo, _uhi; \
    asm("mov.b64 {%0, %1}, %2;" : "=r"(_ulo), "=r"(_uhi) : "l"(s)); \
    lo = __uint_as_float(_ulo); hi = __uint_as_float(_uhi); } while (0)

// smem floats:
//  sW2q [2][128][128] = 32768 | sk [2][50][128] = 12800 | sq [2][128] = 256
//  sAbh [2][128] = 256 | sAq [16][2][128] = 4096 | sWout 256 | s_half [2][64] | s_acc [2][64]
#define SMEM_FLOATS (32768 + 12800 + 256 + 256 + 4096 + 256 + 128 + 128)
#define SMEM_BYTES  (SMEM_FLOATS*4 + 128*4 + 32)

extern "C" __global__ void __launch_bounds__(NT, 1)
din_fused_kernel(const int*   __restrict__ qid_item,
                 const int*   __restrict__ qid_cate,
                 const int*   __restrict__ sid_item,
                 const int*   __restrict__ sid_cate,
                 const int*   __restrict__ mask,    // bool widened to 4B; nonzero == true
                 const float* __restrict__ emb_item,
                 const float* __restrict__ emb_cate,
                 const float* __restrict__ W_hide,
                 const float* __restrict__ b_hide,
                 const float* __restrict__ W_out,
                 const float* __restrict__ b_out,
                 float*       __restrict__ out)
{
    extern __shared__ float smem[];
    float* sW2q   = smem;                     // [2][128 d][128 u]
    float* sk     = sW2q + 32768;             // [2][50][128]
    float* sq     = sk   + 12800;             // [2][128]
    float* sAbh   = sq   + 256;               // [2][128]
    float* sAq    = sAbh + 256;               // [16][2][128]
    float* sWout  = sAq  + 4096;              // [256]
    float* s_half = sWout + UU;               // [2][64]
    float* s_acc  = s_half + 128;             // [2][64]
    int*   sactive= (int*)(s_acc + 128);      // [2][56]
    int*   scnt   = sactive + 112;            // [2][2]

    const int b0   = blockIdx.x << 1;         // batches b0, b0+1
    const int tid  = threadIdx.x;
    const int warp = tid >> 5;
    const int lane = tid & 31;

    // ---------------- Phase 1: gathers + ballot compaction (2 batches) -------
    if (warp < 4) {
        const int bb = warp >> 1;              // batch select
        const int l  = ((warp & 1) << 5) + lane;
        const bool act = (l < LL) && (mask[(size_t)(b0 + bb)*LL + l] != 0);
        const unsigned bal = __ballot_sync(0xffffffffu, act);
        if (lane == 0) scnt[(bb << 1) + (warp & 1)] = __popc(bal);
        // write after counts are visible: defer via second ballot-independent step below
        if (act) {
            // offset within batch: warp&1==1 needs count of previous warp; compute via shfl of bal? 
            // counts not yet in smem reliably -> recompute peer count locally:
            // For warp&1==0 offset=0. For warp&1==1 we need popc of warp (bb,0)'s ballot;
            // handled after __syncthreads below instead.
        }
    }
    if (tid < 256) {
        const int bb = tid >> 7, e = tid & 127;
        const int qi = qid_item[b0 + bb];
        const int qc = qid_cate[b0 + bb];
        sq[(bb << 7) + e] = (e < DD) ? emb_item[(size_t)qi*DD + e]
                                     : emb_cate[(size_t)qc*DD + (e - DD)];
    }
    if (tid >= 256) sWout[tid - 256] = W_out[tid - 256];
    if (tid < 128) s_acc[tid] = 0.f;
    // K gather: 2 batches * 50 * 32 float4 cells
    for (int idx = tid; idx < 2*LL*32; idx += NT) {
        const int bb = idx >= LL*32;
        const int r  = idx - bb*LL*32;
        const int l  = r >> 5;
        const int e4 = r & 31;
        float4 v;
        if (e4 < 16) v = *(const float4*)(emb_item + (size_t)sid_item[(size_t)(b0+bb)*LL + l]*DD + (e4 << 2));
        else         v = *(const float4*)(emb_cate + (size_t)sid_cate[(size_t)(b0+bb)*LL + l]*DD + ((e4 - 16) << 2));
        *(float4*)(sk + bb*6400 + (l << 7) + (e4 << 2)) = v;
    }
    __syncthreads();

    // compaction write (deterministic; counts now visible)
    if (warp < 4) {
        const int bb = warp >> 1;
        const int l  = ((warp & 1) << 5) + lane;
        const bool act = (l < LL) && (mask[(size_t)(b0 + bb)*LL + l] != 0);
        const unsigned bal = __ballot_sync(0xffffffffu, act);
        if (act) {
            const int off = (warp & 1) ? scnt[bb << 1] : 0;
            sactive[bb*56 + off + __popc(bal & ((1u << lane) - 1u))] = l;
        }
    }
    __syncthreads();

    const int nact0 = scnt[0] + scnt[1];
    const int nact1 = scnt[2] + scnt[3];

    // ================= Two passes over u-halves ==============================
    #pragma unroll 1
    for (int h = 0; h < 2; h++) {
        const int gub = h << 7;

        // ---- Phase 2: read Wq/Wk/Wp ONCE, fold for BOTH batches -------------
        {
            const int u4 = lane << 2;          // 4 consecutive local u
            const int d0 = warp << 3;          // 8 d-rows per warp strip
            const int gu = gub + u4;
            const float qb0 = 0.f, qb1 = 0.f; (void)qb0; (void)qb1;
            float4 aq0 = make_float4(0.f,0.f,0.f,0.f);
            float4 aq1 = make_float4(0.f,0.f,0.f,0.f);
            #pragma unroll
            for (int i = 0; i < 8; i++) {
                const int d = d0 + i;
                const float qd0 = sq[d];
                const float qd1 = sq[128 + d];
                const float4 wk = *(const float4*)(W_hide + (size_t)(128 + d)*UU + gu);
                const float4 wp = *(const float4*)(W_hide + (size_t)(256 + d)*UU + gu);
                const float4 wq = *(const float4*)(W_hide + (size_t)d*UU + gu);
                float4 w2;
                w2.x = fmaf(qd0, wp.x, wk.x);
                w2.y = fmaf(qd0, wp.y, wk.y);
                w2.z = fmaf(qd0, wp.z, wk.z);
                w2.w = fmaf(qd0, wp.w, wk.w);
                *(float4*)(sW2q + (d << 7) + u4) = w2;
                w2.x = fmaf(qd1, wp.x, wk.x);
                w2.y = fmaf(qd1, wp.y, wk.y);
                w2.z = fmaf(qd1, wp.z, wk.z);
                w2.w = fmaf(qd1, wp.w, wk.w);
                *(float4*)(sW2q + 16384 + (d << 7) + u4) = w2;
                aq0.x = fmaf(qd0, wq.x, aq0.x);
                aq0.y = fmaf(qd0, wq.y, aq0.y);
                aq0.z = fmaf(qd0, wq.z, aq0.z);
                aq0.w = fmaf(qd0, wq.w, aq0.w);
                aq1.x = fmaf(qd1, wq.x, aq1.x);
                aq1.y = fmaf(qd1, wq.y, aq1.y);
                aq1.z = fmaf(qd1, wq.z, aq1.z);
                aq1.w = fmaf(qd1, wq.w, aq1.w);
            }
            *(float4*)(sAq + warp*256 + u4) = aq0;
            *(float4*)(sAq + warp*256 + 128 + u4) = aq1;
        }
        __syncthreads();
        if (tid < 256) {
            const int bb = tid >> 7, u = tid & 127;
            float a = b_hide[gub + u];
            #pragma unroll
            for (int s = 0; s < 16; s++) a += sAq[s*256 + (bb << 7) + u];
            sAbh[(bb << 7) + u] = a;
        }
        __syncthreads();

        // ---- Phase 3: mainloop (8 l's per warp; warps 0-7 b0, 8-15 b1) ------
        const int bb    = warp >> 3;
        const int wl    = warp & 7;
        const int nact  = bb ? nact1 : nact0;
        const int tiles = (nact + 7) >> 3;

        if (wl < tiles) {
            const float* skb   = sk + bb*6400;
            const float* w2qb  = sW2q + bb*16384;
            const int*   actb  = sactive + bb*56;
            const int i0 = wl << 3;
            int nl = nact - i0; if (nl > 8) nl = 8;

            int koff[8];
            #pragma unroll
            for (int t = 0; t < 8; t++)
                koff[t] = actb[(t < nl) ? i0 + t : i0] << 7;

            const int up = lane << 2;
            const unsigned long long* ab = (const unsigned long long*)(sAbh + (bb << 7) + up);
            const unsigned long long i00 = ab[0], i01 = ab[1];
            unsigned long long A[8][2];
            #pragma unroll
            for (int t = 0; t < 8; t++) { A[t][0] = i00; A[t][1] = i01; }

            for (int d0 = 0; d0 < EE; d0 += 4) {
                float4 kv[8];
                #pragma unroll
                for (int t = 0; t < 8; t++)
                    kv[t] = *(const float4*)(skb + koff[t] + d0);

                #pragma unroll
                for (int dd = 0; dd < 4; dd++) {
                    const ulonglong2 wA = *(const ulonglong2*)(w2qb + ((d0 + dd) << 7) + up);
                    #pragma unroll
                    for (int t = 0; t < 8; t++) {
                        unsigned long long kp;
                        PACK2(kp, ((const float*)&kv[t])[dd]);
                        FFMA2(A[t][0], wA.x, kp);
                        FFMA2(A[t][1], wA.y, kp);
                    }
                }
            }

            const float w0 = sWout[gub+up+0], w1 = sWout[gub+up+1];
            const float w2_= sWout[gub+up+2], w3 = sWout[gub+up+3];
            float s[8];
            #pragma unroll
            for (int t = 0; t < 8; t++) {
                float lo, hi, acc;
                UNPK2(lo, hi, A[t][0]); acc  = fmaxf(lo,0.f)*w0 + fmaxf(hi,0.f)*w1;
                UNPK2(lo, hi, A[t][1]); acc += fmaxf(lo,0.f)*w2_+ fmaxf(hi,0.f)*w3;
                s[t] = acc;
            }
            #pragma unroll
            for (int t = 0; t < 8; t++) {
                #pragma unroll
                for (int off = 16; off > 0; off >>= 1)
                    s[t] += __shfl_xor_sync(0xffffffffu, s[t], off);
            }
            if (lane == 0) {
                #pragma unroll
                for (int t = 0; t < 8; t++)
                    if (t < nl) s_half[(bb << 6) + i0 + t] = s[t];
            }
        }
        __syncthreads();
        if (tid < 128) {
            const int bb2 = tid >> 6, i = tid & 63;
            const int na = bb2 ? nact1 : nact0;
            if (i < na) s_acc[tid] += s_half[tid];
        }
        __syncthreads();
    }

    // ---------------- Phase 4: deterministic weighted sum + store ------------
    if (tid < 256) {
        const int bb = tid >> 7, e = tid & 127;
        const int na = bb ? nact1 : nact0;
        const float bo = b_out[0];
        const float* skb  = sk + bb*6400;
        const int*   actb = sactive + bb*56;
        const float* sab  = s_acc + (bb << 6);
        float acc = 0.f;
        for (int i = 0; i < na; i++)
            acc = fmaf(sab[i] + bo, skb[(actb[i] << 7) + e], acc);
        out[(size_t)(b0 + bb)*EE + e] = acc;
    }
}

extern "C" void kernel_launch(void* const* d_in, const int* in_sizes, int n_in,
                              void* d_out, int out_size)
{
    const int*   qid_item = (const int*)  d_in[0];
    const int*   qid_cate = (const int*)  d_in[1];
    const int*   sid_item = (const int*)  d_in[2];
    const int*   sid_cate = (const int*)  d_in[3];
    const int*   mask     = (const int*)  d_in[4];
    const float* emb_item = (const float*)d_in[5];
    const float* emb_cate = (const float*)d_in[6];
    const float* W_hide   = (const float*)d_in[7];
    const float* b_hide   = (const float*)d_in[8];
    const float* W_out    = (const float*)d_in[9];
    const float* b_out    = (const float*)d_in[10];
    float*       out      = (float*)      d_out;

    const int B = in_sizes[0];   // 4096 (even)

    cudaFuncSetAttribute(din_fused_kernel,
                         cudaFuncAttributeMaxDynamicSharedMemorySize, SMEM_BYTES);

    din_fused_kernel<<<B/2, NT, SMEM_BYTES>>>(
        qid_item, qid_cate, sid_item, sid_cate, mask,
        emb_item, emb_cate, W_hide, b_hide, W_out, b_out, out);
}